// round 5
// baseline (speedup 1.0000x reference)
#include <cuda_runtime.h>
#include <cuda_bf16.h>
#include <math.h>
#include <stdint.h>

#define N_NODES 100000
#define N_EDGES 1600000
#define CH 128
#define OUTC 64
#define NG 64

// ---------------- scratch (static device globals; no allocation) ----------------
__device__ __align__(16) float g_h[N_NODES * CH];   // GEMM output per layer
__device__ __align__(16) float g_x[N_NODES * CH];   // aggregated activation
__device__ float g_dinv[N_NODES];
__device__ int   g_counts[N_NODES];
__device__ int   g_rowstart[N_NODES + 1];
__device__ int   g_fill[N_NODES];
__device__ int   g_col[N_EDGES];
__device__ int   g_bsum[256];
__device__ int   g_boff[256];
__device__ __align__(16) __nv_bfloat16 g_wh[CH * CH];  // W^T hi, [n][k]
__device__ __align__(16) __nv_bfloat16 g_wl[CH * CH];  // W^T lo, [n][k]
__device__ __align__(16) float g_pool[NG * CH];
__device__ float g_cnt[NG];

// ---------------- zero per-call state ----------------
__global__ void k_zero() {
    int i = blockIdx.x * blockDim.x + threadIdx.x;
    if (i < N_NODES) { g_counts[i] = 0; g_fill[i] = 0; }
    if (i < NG * CH) g_pool[i] = 0.f;
    if (i < NG)      g_cnt[i] = 0.f;
}

// ---------------- degree histogram (4 edges/thread, int4 load) ----------------
__global__ void k_count(const int* __restrict__ ei) {
    int e4 = blockIdx.x * blockDim.x + threadIdx.x;   // covers N_EDGES/4
    if (e4 < N_EDGES / 4) {
        int4 d = *(const int4*)(ei + N_EDGES + e4 * 4);
        atomicAdd(&g_counts[d.x], 1);
        atomicAdd(&g_counts[d.y], 1);
        atomicAdd(&g_counts[d.z], 1);
        atomicAdd(&g_counts[d.w], 1);
    }
}

// ---------------- multi-block scan pass 1 (block-local exclusive) ----------------
__global__ __launch_bounds__(512) void k_scan1() {
    __shared__ int sh[512];
    int i = blockIdx.x * 512 + threadIdx.x;
    int v = (i < N_NODES) ? g_counts[i] : 0;
    sh[threadIdx.x] = v;
    __syncthreads();
    #pragma unroll
    for (int d = 1; d < 512; d <<= 1) {
        int t = (threadIdx.x >= d) ? sh[threadIdx.x - d] : 0;
        __syncthreads();
        sh[threadIdx.x] += t;
        __syncthreads();
    }
    if (i < N_NODES) g_rowstart[i] = sh[threadIdx.x] - v;
    if (threadIdx.x == 511) g_bsum[blockIdx.x] = sh[511];
}

// ---------------- pass 2: scan block sums ----------------
__global__ __launch_bounds__(256) void k_scan2(int nblk) {
    __shared__ int sh[256];
    int t = threadIdx.x;
    int v = (t < nblk) ? g_bsum[t] : 0;
    sh[t] = v;
    __syncthreads();
    #pragma unroll
    for (int d = 1; d < 256; d <<= 1) {
        int tv = (t >= d) ? sh[t - d] : 0;
        __syncthreads();
        sh[t] += tv;
        __syncthreads();
    }
    g_boff[t] = sh[t] - v;
}

// ---------------- pass 3: add offsets; fused dinv ----------------
__global__ void k_scan3() {
    int i = blockIdx.x * blockDim.x + threadIdx.x;
    if (i < N_NODES) {
        g_rowstart[i] += g_boff[i >> 9];
        g_dinv[i] = rsqrtf((float)g_counts[i] + 1.0f);
    }
    if (i == 0) g_rowstart[N_NODES] = N_EDGES;
}

// ---------------- CSR fill (4 edges/thread) ----------------
__global__ void k_fill(const int* __restrict__ ei) {
    int e4 = blockIdx.x * blockDim.x + threadIdx.x;
    if (e4 < N_EDGES / 4) {
        int4 s = *(const int4*)(ei + e4 * 4);
        int4 d = *(const int4*)(ei + N_EDGES + e4 * 4);
        g_col[g_rowstart[d.x] + atomicAdd(&g_fill[d.x], 1)] = s.x;
        g_col[g_rowstart[d.y] + atomicAdd(&g_fill[d.y], 1)] = s.y;
        g_col[g_rowstart[d.z] + atomicAdd(&g_fill[d.z], 1)] = s.z;
        g_col[g_rowstart[d.w] + atomicAdd(&g_fill[d.w], 1)] = s.w;
    }
}

// ---------------- weight convert: W[k][n] fp32 -> W^T hi/lo bf16 [n][k] ----------------
__global__ void k_wconv(const float* __restrict__ W) {
    int i = blockIdx.x * blockDim.x + threadIdx.x;   // i = n*128 + k
    if (i < CH * CH) {
        int n = i >> 7, k = i & 127;
        float w = W[k * CH + n];
        __nv_bfloat16 h = __float2bfloat16(w);
        __nv_bfloat16 l = __float2bfloat16(w - __bfloat162float(h));
        g_wh[i] = h;
        g_wl[i] = l;
    }
}

// ---------------- mma.sync bf16 GEMM with hi/lo split ----------------
#define SM_AHI 0
#define SM_ALO (64 * 136 * 2)
#define SM_BHI (SM_ALO + 64 * 136 * 2)
#define SM_BLO (SM_BHI + 128 * 136 * 2)
#define SM_MMA_TOTAL (SM_BLO + 128 * 136 * 2)   // 104448 B

__device__ __forceinline__ void mma16816(float* c, const uint32_t* a, const uint32_t* b) {
    asm volatile("mma.sync.aligned.m16n8k16.row.col.f32.bf16.bf16.f32 "
                 "{%0,%1,%2,%3}, {%4,%5,%6,%7}, {%8,%9}, {%0,%1,%2,%3};"
                 : "+f"(c[0]), "+f"(c[1]), "+f"(c[2]), "+f"(c[3])
                 : "r"(a[0]), "r"(a[1]), "r"(a[2]), "r"(a[3]), "r"(b[0]), "r"(b[1]));
}
__device__ __forceinline__ uint32_t pack_bf2(float a, float b) {
    __nv_bfloat16 x = __float2bfloat16(a), y = __float2bfloat16(b);
    return (uint32_t)__bfloat16_as_ushort(x) | ((uint32_t)__bfloat16_as_ushort(y) << 16);
}

__global__ __launch_bounds__(256, 2) void k_gemm_mma(const float* __restrict__ X,
                                                     const float* __restrict__ B,
                                                     float* __restrict__ O) {
    extern __shared__ char smem[];
    int tid = threadIdx.x;
    int wid = tid >> 5;
    int lane = tid & 31;
    int m0 = blockIdx.x * 64;
    int m_w = (wid & 1) * 32;
    int n_w = (wid >> 1) * 32;

    for (int p = tid; p < 64 * 32; p += 256) {
        int row = p >> 5;
        int c4 = (p & 31) * 4;
        int gr = m0 + row;
        if (gr >= N_NODES) gr = 0;
        float4 v = *(const float4*)(X + (size_t)gr * CH + c4);
        float hx = __bfloat162float(__float2bfloat16(v.x));
        float hy = __bfloat162float(__float2bfloat16(v.y));
        float hz = __bfloat162float(__float2bfloat16(v.z));
        float hw = __bfloat162float(__float2bfloat16(v.w));
        uint32_t hp0 = pack_bf2(v.x, v.y), hp1 = pack_bf2(v.z, v.w);
        uint32_t lp0 = pack_bf2(v.x - hx, v.y - hy), lp1 = pack_bf2(v.z - hz, v.w - hw);
        char* ah = smem + SM_AHI + row * 272 + c4 * 2;
        char* al = smem + SM_ALO + row * 272 + c4 * 2;
        *(uint2*)ah = make_uint2(hp0, hp1);
        *(uint2*)al = make_uint2(lp0, lp1);
    }
    for (int p = tid; p < 128 * 16; p += 256) {
        int n = p >> 4;
        int k8 = (p & 15) * 8;
        uint4 vh = *(const uint4*)(g_wh + n * CH + k8);
        uint4 vl = *(const uint4*)(g_wl + n * CH + k8);
        *(uint4*)(smem + SM_BHI + n * 272 + k8 * 2) = vh;
        *(uint4*)(smem + SM_BLO + n * 272 + k8 * 2) = vl;
    }
    __syncthreads();

    float acc[2][4][4];
    #pragma unroll
    for (int mt = 0; mt < 2; mt++)
        #pragma unroll
        for (int nt = 0; nt < 4; nt++)
            #pragma unroll
            for (int j = 0; j < 4; j++) acc[mt][nt][j] = 0.f;

    int q = lane >> 2;
    int km = (lane & 3) * 2;

    #pragma unroll
    for (int ks = 0; ks < 8; ks++) {
        int k0 = ks * 16;
        uint32_t ah[2][4], al[2][4], bh[4][2], bl[4][2];
        #pragma unroll
        for (int mt = 0; mt < 2; mt++) {
            int r = m_w + mt * 16 + q;
            const char* pa = smem + r * 272 + (k0 + km) * 2;
            ah[mt][0] = *(const uint32_t*)(pa + SM_AHI);
            ah[mt][1] = *(const uint32_t*)(pa + SM_AHI + 8 * 272);
            ah[mt][2] = *(const uint32_t*)(pa + SM_AHI + 16);
            ah[mt][3] = *(const uint32_t*)(pa + SM_AHI + 8 * 272 + 16);
            al[mt][0] = *(const uint32_t*)(pa + SM_ALO);
            al[mt][1] = *(const uint32_t*)(pa + SM_ALO + 8 * 272);
            al[mt][2] = *(const uint32_t*)(pa + SM_ALO + 16);
            al[mt][3] = *(const uint32_t*)(pa + SM_ALO + 8 * 272 + 16);
        }
        #pragma unroll
        for (int nt = 0; nt < 4; nt++) {
            int n = n_w + nt * 8 + q;
            const char* pb = smem + n * 272 + (k0 + km) * 2;
            bh[nt][0] = *(const uint32_t*)(pb + SM_BHI);
            bh[nt][1] = *(const uint32_t*)(pb + SM_BHI + 16);
            bl[nt][0] = *(const uint32_t*)(pb + SM_BLO);
            bl[nt][1] = *(const uint32_t*)(pb + SM_BLO + 16);
        }
        #pragma unroll
        for (int mt = 0; mt < 2; mt++)
            #pragma unroll
            for (int nt = 0; nt < 4; nt++) {
                mma16816(acc[mt][nt], ah[mt], bh[nt]);
                mma16816(acc[mt][nt], ah[mt], bl[nt]);
                mma16816(acc[mt][nt], al[mt], bh[nt]);
            }
    }

    #pragma unroll
    for (int nt = 0; nt < 4; nt++) {
        int c = n_w + nt * 8 + km;
        float bx = __ldg(B + c), by = __ldg(B + c + 1);
        #pragma unroll
        for (int mt = 0; mt < 2; mt++) {
            int r0 = m0 + m_w + mt * 16 + q;
            if (r0 < N_NODES)
                *(float2*)(O + (size_t)r0 * CH + c) =
                    make_float2(acc[mt][nt][0] + bx, acc[mt][nt][1] + by);
            int r1 = r0 + 8;
            if (r1 < N_NODES)
                *(float2*)(O + (size_t)r1 * CH + c) =
                    make_float2(acc[mt][nt][2] + bx, acc[mt][nt][3] + by);
        }
    }
}

// ---------------- CSR gather aggregation ----------------
__global__ __launch_bounds__(256) void k_agg(const float* __restrict__ H,
                                             float* __restrict__ O, int relu) {
    int node = blockIdx.x * 8 + (threadIdx.x >> 5);
    if (node >= N_NODES) return;
    int lane = threadIdx.x & 31;
    const float4* H4 = (const float4*)H;

    float dn = g_dinv[node];
    float4 hn = H4[node * 32 + lane];
    float4 acc = make_float4(dn * hn.x, dn * hn.y, dn * hn.z, dn * hn.w);

    int beg = g_rowstart[node];
    int end = g_rowstart[node + 1];
    #pragma unroll 4
    for (int e = beg; e < end; e++) {
        int s = g_col[e];
        float w = g_dinv[s];
        float4 hs = H4[s * 32 + lane];
        acc.x += w * hs.x;
        acc.y += w * hs.y;
        acc.z += w * hs.z;
        acc.w += w * hs.w;
    }
    acc.x *= dn; acc.y *= dn; acc.z *= dn; acc.w *= dn;
    if (relu) {
        acc.x = fmaxf(acc.x, 0.f); acc.y = fmaxf(acc.y, 0.f);
        acc.z = fmaxf(acc.z, 0.f); acc.w = fmaxf(acc.w, 0.f);
    }
    ((float4*)O)[node * 32 + lane] = acc;
}

// ---------------- mean-pool accumulation ----------------
__global__ __launch_bounds__(256) void k_pool(const float* __restrict__ H,
                                              const int* __restrict__ batch) {
    int node = blockIdx.x * 8 + (threadIdx.x >> 5);
    if (node >= N_NODES) return;
    int lane = threadIdx.x & 31;
    int g = batch[node];
    float4 v = ((const float4*)H)[node * 32 + lane];
    float* dst = &g_pool[g * CH + lane * 4];
    asm volatile("red.global.add.v4.f32 [%0], {%1,%2,%3,%4};"
                 :: "l"(dst), "f"(v.x), "f"(v.y), "f"(v.z), "f"(v.w) : "memory");
    if (lane == 0) atomicAdd(&g_cnt[g], 1.0f);
}

// ---------------- final projection ----------------
__global__ void k_final(const float* __restrict__ Wp, const float* __restrict__ bp,
                        float* __restrict__ out) {
    int g = blockIdx.x;
    int j = threadIdx.x;
    float inv = 1.0f / fmaxf(g_cnt[g], 1.0f);
    float acc = bp[j];
    #pragma unroll 4
    for (int c = 0; c < CH; c++)
        acc += g_pool[g * CH + c] * inv * Wp[c * OUTC + j];
    out[g * OUTC + j] = acc;
}

// ---------------- launch ----------------
extern "C" void kernel_launch(void* const* d_in, const int* in_sizes, int n_in,
                              void* d_out, int out_size) {
    const float* x   = (const float*)d_in[0];
    const int*   ei  = (const int*)d_in[1];
    const int*   bat = (const int*)d_in[2];
    const float* W1 = (const float*)d_in[3];
    const float* b1 = (const float*)d_in[4];
    const float* W2 = (const float*)d_in[5];
    const float* b2 = (const float*)d_in[6];
    const float* W3 = (const float*)d_in[7];
    const float* b3 = (const float*)d_in[8];
    const float* Wp = (const float*)d_in[9];
    const float* bp = (const float*)d_in[10];
    float* out = (float*)d_out;

    void *ph, *px;
    cudaGetSymbolAddress(&ph, g_h);
    cudaGetSymbolAddress(&px, g_x);
    float* hbuf = (float*)ph;
    float* xbuf = (float*)px;

    // one-time resource setup (first call = uncaptured correctness run)
    static cudaStream_t sB = nullptr;
    static cudaEvent_t ev_fork = nullptr, ev_csr = nullptr;
    if (sB == nullptr) {
        cudaFuncSetAttribute(k_gemm_mma, cudaFuncAttributeMaxDynamicSharedMemorySize, SM_MMA_TOTAL);
        cudaStreamCreateWithFlags(&sB, cudaStreamNonBlocking);
        cudaEventCreateWithFlags(&ev_fork, cudaEventDisableTiming);
        cudaEventCreateWithFlags(&ev_csr, cudaEventDisableTiming);
    }

    int nb_nodes = (N_NODES + 255) / 256;
    int nb_e4    = (N_EDGES / 4 + 255) / 256;
    int nb_warp8 = (N_NODES + 7) / 8;
    int nb_gemm  = (N_NODES + 63) / 64;
    int nb_scan1 = (N_NODES + 511) / 512;   // 196
    int nb_w     = (CH * CH + 255) / 256;

    // fork: CSR build on stream B, concurrent with wconv1+gemm1 on main stream
    cudaEventRecord(ev_fork, 0);
    cudaStreamWaitEvent(sB, ev_fork, 0);

    k_zero <<<nb_nodes, 256, 0, sB>>>();
    k_count<<<nb_e4,    256, 0, sB>>>(ei);
    k_scan1<<<nb_scan1, 512, 0, sB>>>();
    k_scan2<<<1,        256, 0, sB>>>(nb_scan1);
    k_scan3<<<nb_nodes, 256, 0, sB>>>();
    k_fill <<<nb_e4,    256, 0, sB>>>(ei);
    cudaEventRecord(ev_csr, sB);

    // main stream: layer-1 GEMM (independent of CSR)
    k_wconv<<<nb_w, 256>>>(W1);
    k_gemm_mma<<<nb_gemm, 256, SM_MMA_TOTAL>>>(x, b1, hbuf);

    // join: agg needs CSR + dinv
    cudaStreamWaitEvent(0, ev_csr, 0);

    k_agg<<<nb_warp8, 256>>>(hbuf, xbuf, 1);
    // layer 2
    k_wconv<<<nb_w, 256>>>(W2);
    k_gemm_mma<<<nb_gemm, 256, SM_MMA_TOTAL>>>(xbuf, b2, hbuf);
    k_agg<<<nb_warp8, 256>>>(hbuf, xbuf, 1);
    // layer 3
    k_wconv<<<nb_w, 256>>>(W3);
    k_gemm_mma<<<nb_gemm, 256, SM_MMA_TOTAL>>>(xbuf, b3, hbuf);
    k_agg<<<nb_warp8, 256>>>(hbuf, xbuf, 0);

    // pooling + projection
    k_pool<<<nb_warp8, 256>>>(xbuf, bat);
    k_final<<<NG, OUTC>>>(Wp, bp, out);
}

// round 6
// speedup vs baseline: 1.1968x; 1.1968x over previous
#include <cuda_runtime.h>
#include <cuda_bf16.h>
#include <math.h>
#include <stdint.h>

#define N_NODES 100000
#define N_EDGES 1600000
#define CH 128
#define OUTC 64
#define NG 64

// ---------------- scratch (static device globals; no allocation) ----------------
__device__ __align__(16) uint32_t g_hb[N_NODES * 64];   // packed bf16x2 messages dinv*(h+b)
__device__ __align__(16) uint32_t g_xh[N_NODES * 64];   // activation hi (bf16x2)
__device__ __align__(16) uint32_t g_xl[N_NODES * 64];   // activation lo (bf16x2)
__device__ float g_dinv[N_NODES];
__device__ int   g_counts[N_NODES];
__device__ int   g_rowstart[N_NODES + 1];
__device__ int   g_fill[N_NODES];
__device__ int   g_col[N_EDGES];
__device__ int   g_bsum[256];
__device__ int   g_boff[256];
__device__ __align__(16) __nv_bfloat16 g_wh[3 * CH * CH];  // W^T hi, [layer][n][k]
__device__ __align__(16) __nv_bfloat16 g_wl[3 * CH * CH];  // W^T lo
__device__ __align__(16) float g_pool[NG * CH];
__device__ float g_cnt[NG];

__device__ __forceinline__ float bflo(uint32_t u) {
    return __bfloat162float(__ushort_as_bfloat16((unsigned short)(u & 0xFFFF)));
}
__device__ __forceinline__ float bfhi(uint32_t u) {
    return __bfloat162float(__ushort_as_bfloat16((unsigned short)(u >> 16)));
}
__device__ __forceinline__ uint32_t pack_bf2(float a, float b) {
    __nv_bfloat16 x = __float2bfloat16(a), y = __float2bfloat16(b);
    return (uint32_t)__bfloat16_as_ushort(x) | ((uint32_t)__bfloat16_as_ushort(y) << 16);
}

// ---------------- zero per-call state ----------------
__global__ void k_zero() {
    int i = blockIdx.x * blockDim.x + threadIdx.x;
    if (i < N_NODES) { g_counts[i] = 0; g_fill[i] = 0; }
    if (i < NG * CH) g_pool[i] = 0.f;
    if (i < NG)      g_cnt[i] = 0.f;
}

// ---------------- degree histogram (4 edges/thread) ----------------
__global__ void k_count(const int* __restrict__ ei) {
    int e4 = blockIdx.x * blockDim.x + threadIdx.x;
    if (e4 < N_EDGES / 4) {
        int4 d = *(const int4*)(ei + N_EDGES + e4 * 4);
        atomicAdd(&g_counts[d.x], 1);
        atomicAdd(&g_counts[d.y], 1);
        atomicAdd(&g_counts[d.z], 1);
        atomicAdd(&g_counts[d.w], 1);
    }
}

// ---------------- multi-block scan pass 1 ----------------
__global__ __launch_bounds__(512) void k_scan1() {
    __shared__ int sh[512];
    int i = blockIdx.x * 512 + threadIdx.x;
    int v = (i < N_NODES) ? g_counts[i] : 0;
    sh[threadIdx.x] = v;
    __syncthreads();
    #pragma unroll
    for (int d = 1; d < 512; d <<= 1) {
        int t = (threadIdx.x >= d) ? sh[threadIdx.x - d] : 0;
        __syncthreads();
        sh[threadIdx.x] += t;
        __syncthreads();
    }
    if (i < N_NODES) g_rowstart[i] = sh[threadIdx.x] - v;
    if (threadIdx.x == 511) g_bsum[blockIdx.x] = sh[511];
}

// ---------------- pass 2 ----------------
__global__ __launch_bounds__(256) void k_scan2(int nblk) {
    __shared__ int sh[256];
    int t = threadIdx.x;
    int v = (t < nblk) ? g_bsum[t] : 0;
    sh[t] = v;
    __syncthreads();
    #pragma unroll
    for (int d = 1; d < 256; d <<= 1) {
        int tv = (t >= d) ? sh[t - d] : 0;
        __syncthreads();
        sh[t] += tv;
        __syncthreads();
    }
    g_boff[t] = sh[t] - v;
}

// ---------------- pass 3 + dinv ----------------
__global__ void k_scan3() {
    int i = blockIdx.x * blockDim.x + threadIdx.x;
    if (i < N_NODES) {
        g_rowstart[i] += g_boff[i >> 9];
        g_dinv[i] = rsqrtf((float)g_counts[i] + 1.0f);
    }
    if (i == 0) g_rowstart[N_NODES] = N_EDGES;
}

// ---------------- CSR fill ----------------
__global__ void k_fill(const int* __restrict__ ei) {
    int e4 = blockIdx.x * blockDim.x + threadIdx.x;
    if (e4 < N_EDGES / 4) {
        int4 s = *(const int4*)(ei + e4 * 4);
        int4 d = *(const int4*)(ei + N_EDGES + e4 * 4);
        g_col[g_rowstart[d.x] + atomicAdd(&g_fill[d.x], 1)] = s.x;
        g_col[g_rowstart[d.y] + atomicAdd(&g_fill[d.y], 1)] = s.y;
        g_col[g_rowstart[d.z] + atomicAdd(&g_fill[d.z], 1)] = s.z;
        g_col[g_rowstart[d.w] + atomicAdd(&g_fill[d.w], 1)] = s.w;
    }
}

// ---------------- weight convert, all 3 layers ----------------
__global__ void k_wconv3(const float* __restrict__ W1, const float* __restrict__ W2,
                         const float* __restrict__ W3) {
    int i = blockIdx.x * blockDim.x + threadIdx.x;   // i = l*16384 + n*128 + k
    if (i < 3 * CH * CH) {
        int l = i >> 14;
        int n = (i >> 7) & 127, k = i & 127;
        const float* W = (l == 0) ? W1 : (l == 1) ? W2 : W3;
        float w = W[k * CH + n];
        __nv_bfloat16 h = __float2bfloat16(w);
        __nv_bfloat16 lo = __float2bfloat16(w - __bfloat162float(h));
        g_wh[i] = h;
        g_wl[i] = lo;
    }
}

// ---------------- mma.sync bf16 GEMM with hi/lo split ----------------
// O(packed bf16 messages)[n][c] = dinv[n] * (X[n,:] @ W[:,c] + b[c])
#define SM_AHI 0
#define SM_ALO (64 * 136 * 2)
#define SM_BHI (SM_ALO + 64 * 136 * 2)
#define SM_BLO (SM_BHI + 128 * 136 * 2)
#define SM_MMA_TOTAL (SM_BLO + 128 * 136 * 2)   // 104448 B

__device__ __forceinline__ void mma16816(float* c, const uint32_t* a, const uint32_t* b) {
    asm volatile("mma.sync.aligned.m16n8k16.row.col.f32.bf16.bf16.f32 "
                 "{%0,%1,%2,%3}, {%4,%5,%6,%7}, {%8,%9}, {%0,%1,%2,%3};"
                 : "+f"(c[0]), "+f"(c[1]), "+f"(c[2]), "+f"(c[3])
                 : "r"(a[0]), "r"(a[1]), "r"(a[2]), "r"(a[3]), "r"(b[0]), "r"(b[1]));
}

__global__ __launch_bounds__(256, 2) void k_gemm_mma(int mode,
                                                     const float* __restrict__ X,
                                                     const uint32_t* __restrict__ XH,
                                                     const uint32_t* __restrict__ XL,
                                                     int layer,
                                                     const float* __restrict__ B,
                                                     uint32_t* __restrict__ O) {
    extern __shared__ char smem[];
    int tid = threadIdx.x;
    int wid = tid >> 5;
    int lane = tid & 31;
    int m0 = blockIdx.x * 64;
    int m_w = (wid & 1) * 32;
    int n_w = (wid >> 1) * 32;

    if (mode == 0) {
        // layer 1: fp32 input, split here
        for (int p = tid; p < 64 * 32; p += 256) {
            int row = p >> 5;
            int c4 = (p & 31) * 4;
            int gr = m0 + row;
            if (gr >= N_NODES) gr = 0;
            float4 v = *(const float4*)(X + (size_t)gr * CH + c4);
            float hx = __bfloat162float(__float2bfloat16(v.x));
            float hy = __bfloat162float(__float2bfloat16(v.y));
            float hz = __bfloat162float(__float2bfloat16(v.z));
            float hw = __bfloat162float(__float2bfloat16(v.w));
            uint32_t hp0 = pack_bf2(v.x, v.y), hp1 = pack_bf2(v.z, v.w);
            uint32_t lp0 = pack_bf2(v.x - hx, v.y - hy), lp1 = pack_bf2(v.z - hz, v.w - hw);
            char* ah = smem + SM_AHI + row * 272 + c4 * 2;
            char* al = smem + SM_ALO + row * 272 + c4 * 2;
            *(uint2*)ah = make_uint2(hp0, hp1);
            *(uint2*)al = make_uint2(lp0, lp1);
        }
    } else {
        // layers 2/3: prepacked hi/lo input — straight copy
        for (int p = tid; p < 64 * 16; p += 256) {
            int row = p >> 4;
            int j = p & 15;                 // uint4 index (8 channels)
            int gr = m0 + row;
            if (gr >= N_NODES) gr = 0;
            uint4 vh = ((const uint4*)(XH + (size_t)gr * 64))[j];
            uint4 vl = ((const uint4*)(XL + (size_t)gr * 64))[j];
            *(uint4*)(smem + SM_AHI + row * 272 + j * 16) = vh;
            *(uint4*)(smem + SM_ALO + row * 272 + j * 16) = vl;
        }
    }
    {
        const __nv_bfloat16* wh = g_wh + layer * CH * CH;
        const __nv_bfloat16* wl = g_wl + layer * CH * CH;
        for (int p = tid; p < 128 * 16; p += 256) {
            int n = p >> 4;
            int k8 = (p & 15) * 8;
            uint4 vh = *(const uint4*)(wh + n * CH + k8);
            uint4 vl = *(const uint4*)(wl + n * CH + k8);
            *(uint4*)(smem + SM_BHI + n * 272 + k8 * 2) = vh;
            *(uint4*)(smem + SM_BLO + n * 272 + k8 * 2) = vl;
        }
    }
    __syncthreads();

    float acc[2][4][4];
    #pragma unroll
    for (int mt = 0; mt < 2; mt++)
        #pragma unroll
        for (int nt = 0; nt < 4; nt++)
            #pragma unroll
            for (int j = 0; j < 4; j++) acc[mt][nt][j] = 0.f;

    int q = lane >> 2;
    int km = (lane & 3) * 2;

    #pragma unroll
    for (int ks = 0; ks < 8; ks++) {
        int k0 = ks * 16;
        uint32_t ah[2][4], al[2][4], bh[4][2], bl[4][2];
        #pragma unroll
        for (int mt = 0; mt < 2; mt++) {
            int r = m_w + mt * 16 + q;
            const char* pa = smem + r * 272 + (k0 + km) * 2;
            ah[mt][0] = *(const uint32_t*)(pa + SM_AHI);
            ah[mt][1] = *(const uint32_t*)(pa + SM_AHI + 8 * 272);
            ah[mt][2] = *(const uint32_t*)(pa + SM_AHI + 16);
            ah[mt][3] = *(const uint32_t*)(pa + SM_AHI + 8 * 272 + 16);
            al[mt][0] = *(const uint32_t*)(pa + SM_ALO);
            al[mt][1] = *(const uint32_t*)(pa + SM_ALO + 8 * 272);
            al[mt][2] = *(const uint32_t*)(pa + SM_ALO + 16);
            al[mt][3] = *(const uint32_t*)(pa + SM_ALO + 8 * 272 + 16);
        }
        #pragma unroll
        for (int nt = 0; nt < 4; nt++) {
            int n = n_w + nt * 8 + q;
            const char* pb = smem + n * 272 + (k0 + km) * 2;
            bh[nt][0] = *(const uint32_t*)(pb + SM_BHI);
            bh[nt][1] = *(const uint32_t*)(pb + SM_BHI + 16);
            bl[nt][0] = *(const uint32_t*)(pb + SM_BLO);
            bl[nt][1] = *(const uint32_t*)(pb + SM_BLO + 16);
        }
        #pragma unroll
        for (int mt = 0; mt < 2; mt++)
            #pragma unroll
            for (int nt = 0; nt < 4; nt++) {
                mma16816(acc[mt][nt], ah[mt], bh[nt]);
                mma16816(acc[mt][nt], ah[mt], bl[nt]);
                mma16816(acc[mt][nt], al[mt], bh[nt]);
            }
    }

    // epilogue: bias, scale by dinv[row], pack bf16x2
    #pragma unroll
    for (int nt = 0; nt < 4; nt++) {
        int c = n_w + nt * 8 + km;
        float bx = __ldg(B + c), by = __ldg(B + c + 1);
        #pragma unroll
        for (int mt = 0; mt < 2; mt++) {
            int r0 = m0 + m_w + mt * 16 + q;
            if (r0 < N_NODES) {
                float dr = g_dinv[r0];
                O[(size_t)r0 * 64 + (c >> 1)] =
                    pack_bf2(dr * (acc[mt][nt][0] + bx), dr * (acc[mt][nt][1] + by));
            }
            int r1 = r0 + 8;
            if (r1 < N_NODES) {
                float dr = g_dinv[r1];
                O[(size_t)r1 * 64 + (c >> 1)] =
                    pack_bf2(dr * (acc[mt][nt][2] + bx), dr * (acc[mt][nt][3] + by));
            }
        }
    }
}

// ---------------- CSR gather aggregation over packed bf16 messages ----------------
// out[n] = dinv[n] * (sum_s m[s] + m[n]); mode 0: relu + write hi/lo; mode 1: pool.
__global__ __launch_bounds__(256) void k_agg(const uint32_t* __restrict__ Hb,
                                             uint32_t* __restrict__ XH,
                                             uint32_t* __restrict__ XL,
                                             const int* __restrict__ batch,
                                             int mode) {
    int node = blockIdx.x * 8 + (threadIdx.x >> 5);
    if (node >= N_NODES) return;
    int lane = threadIdx.x & 31;
    const uint2* H2 = (const uint2*)Hb;

    uint2 hn = H2[(size_t)node * 32 + lane];
    float a0 = bflo(hn.x), a1 = bfhi(hn.x), a2 = bflo(hn.y), a3 = bfhi(hn.y);

    int beg = g_rowstart[node];
    int end = g_rowstart[node + 1];
    #pragma unroll 4
    for (int e = beg; e < end; e++) {
        int s = g_col[e];
        uint2 hs = H2[(size_t)s * 32 + lane];
        a0 += bflo(hs.x);
        a1 += bfhi(hs.x);
        a2 += bflo(hs.y);
        a3 += bfhi(hs.y);
    }
    float dn = g_dinv[node];
    a0 *= dn; a1 *= dn; a2 *= dn; a3 *= dn;

    if (mode == 0) {
        a0 = fmaxf(a0, 0.f); a1 = fmaxf(a1, 0.f);
        a2 = fmaxf(a2, 0.f); a3 = fmaxf(a3, 0.f);
        float h0 = __bfloat162float(__float2bfloat16(a0));
        float h1 = __bfloat162float(__float2bfloat16(a1));
        float h2 = __bfloat162float(__float2bfloat16(a2));
        float h3 = __bfloat162float(__float2bfloat16(a3));
        ((uint2*)XH)[(size_t)node * 32 + lane] = make_uint2(pack_bf2(a0, a1), pack_bf2(a2, a3));
        ((uint2*)XL)[(size_t)node * 32 + lane] =
            make_uint2(pack_bf2(a0 - h0, a1 - h1), pack_bf2(a2 - h2, a3 - h3));
    } else {
        int g = batch[node];
        float* dst = &g_pool[g * CH + lane * 4];
        asm volatile("red.global.add.v4.f32 [%0], {%1,%2,%3,%4};"
                     :: "l"(dst), "f"(a0), "f"(a1), "f"(a2), "f"(a3) : "memory");
        if (lane == 0) atomicAdd(&g_cnt[g], 1.0f);
    }
}

// ---------------- final projection ----------------
__global__ void k_final(const float* __restrict__ Wp, const float* __restrict__ bp,
                        float* __restrict__ out) {
    int g = blockIdx.x;
    int j = threadIdx.x;
    float inv = 1.0f / fmaxf(g_cnt[g], 1.0f);
    float acc = bp[j];
    #pragma unroll 4
    for (int c = 0; c < CH; c++)
        acc += g_pool[g * CH + c] * inv * Wp[c * OUTC + j];
    out[g * OUTC + j] = acc;
}

// ---------------- launch ----------------
extern "C" void kernel_launch(void* const* d_in, const int* in_sizes, int n_in,
                              void* d_out, int out_size) {
    const float* x   = (const float*)d_in[0];
    const int*   ei  = (const int*)d_in[1];
    const int*   bat = (const int*)d_in[2];
    const float* W1 = (const float*)d_in[3];
    const float* b1 = (const float*)d_in[4];
    const float* W2 = (const float*)d_in[5];
    const float* b2 = (const float*)d_in[6];
    const float* W3 = (const float*)d_in[7];
    const float* b3 = (const float*)d_in[8];
    const float* Wp = (const float*)d_in[9];
    const float* bp = (const float*)d_in[10];
    float* out = (float*)d_out;

    void *phb, *pxh, *pxl;
    cudaGetSymbolAddress(&phb, g_hb);
    cudaGetSymbolAddress(&pxh, g_xh);
    cudaGetSymbolAddress(&pxl, g_xl);
    uint32_t* hb = (uint32_t*)phb;
    uint32_t* xh = (uint32_t*)pxh;
    uint32_t* xl = (uint32_t*)pxl;

    static cudaStream_t sB = nullptr;
    static cudaEvent_t ev_fork = nullptr, ev_dinv = nullptr, ev_csr = nullptr;
    if (sB == nullptr) {
        cudaFuncSetAttribute(k_gemm_mma, cudaFuncAttributeMaxDynamicSharedMemorySize, SM_MMA_TOTAL);
        cudaStreamCreateWithFlags(&sB, cudaStreamNonBlocking);
        cudaEventCreateWithFlags(&ev_fork, cudaEventDisableTiming);
        cudaEventCreateWithFlags(&ev_dinv, cudaEventDisableTiming);
        cudaEventCreateWithFlags(&ev_csr, cudaEventDisableTiming);
    }

    int nb_nodes = (N_NODES + 255) / 256;
    int nb_e4    = (N_EDGES / 4 + 255) / 256;
    int nb_warp8 = (N_NODES + 7) / 8;
    int nb_gemm  = (N_NODES + 63) / 64;
    int nb_scan1 = (N_NODES + 511) / 512;   // 196
    int nb_w3    = (3 * CH * CH + 255) / 256;

    // fork: CSR+dinv build on stream B
    cudaEventRecord(ev_fork, 0);
    cudaStreamWaitEvent(sB, ev_fork, 0);
    k_zero <<<nb_nodes, 256, 0, sB>>>();
    k_count<<<nb_e4,    256, 0, sB>>>(ei);
    k_scan1<<<nb_scan1, 512, 0, sB>>>();
    k_scan2<<<1,        256, 0, sB>>>(nb_scan1);
    k_scan3<<<nb_nodes, 256, 0, sB>>>();
    cudaEventRecord(ev_dinv, sB);
    k_fill <<<nb_e4,    256, 0, sB>>>(ei);
    cudaEventRecord(ev_csr, sB);

    // main: weight conversion (independent), then gemm1 (needs dinv)
    k_wconv3<<<nb_w3, 256>>>(W1, W2, W3);
    cudaStreamWaitEvent(0, ev_dinv, 0);
    k_gemm_mma<<<nb_gemm, 256, SM_MMA_TOTAL>>>(0, x, nullptr, nullptr, 0, b1, hb);
    cudaStreamWaitEvent(0, ev_csr, 0);

    k_agg<<<nb_warp8, 256>>>(hb, xh, xl, bat, 0);
    k_gemm_mma<<<nb_gemm, 256, SM_MMA_TOTAL>>>(1, nullptr, xh, xl, 1, b2, hb);
    k_agg<<<nb_warp8, 256>>>(hb, xh, xl, bat, 0);
    k_gemm_mma<<<nb_gemm, 256, SM_MMA_TOTAL>>>(1, nullptr, xh, xl, 2, b3, hb);
    k_agg<<<nb_warp8, 256>>>(hb, xh, xl, bat, 1);   // fused pooling

    k_final<<<NG, OUTC>>>(Wp, bp, out);
}